// round 7
// baseline (speedup 1.0000x reference)
#include <cuda_runtime.h>
#include <cuda_bf16.h>
#include <math.h>
#include <stdint.h>

// Problem constants
#define TSEQ    2048
#define BATCH   2
#define DMODEL  1024
#define NHEAD   16
#define HEADDIM 64
#define FFDIM   4096
#define NLAYER  4
#define ROWS    (BATCH * TSEQ)          // 4096
#define QKVDIM  (3 * DMODEL)            // 3072

// -------------------- scratch (allocation-free) --------------------
__device__ float g_x  [ROWS * DMODEL];          // residual stream (fp32)
__device__ float g_qkv[ROWS * QKVDIM];          // qkv projection (fp32)
// dual-bf16 activation planes
__device__ __nv_bfloat16 g_xn_h [ROWS * DMODEL];
__device__ __nv_bfloat16 g_xn_l [ROWS * DMODEL];
__device__ __nv_bfloat16 g_att_h[ROWS * DMODEL];
__device__ __nv_bfloat16 g_att_l[ROWS * DMODEL];
__device__ __nv_bfloat16 g_h_h  [ROWS * FFDIM];
__device__ __nv_bfloat16 g_h_l  [ROWS * FFDIM];
// dual-bf16 weight planes (split per launch)
__device__ __nv_bfloat16 g_wi_h[NLAYER * QKVDIM * DMODEL];
__device__ __nv_bfloat16 g_wi_l[NLAYER * QKVDIM * DMODEL];
__device__ __nv_bfloat16 g_wo_h[NLAYER * DMODEL * DMODEL];
__device__ __nv_bfloat16 g_wo_l[NLAYER * DMODEL * DMODEL];
__device__ __nv_bfloat16 g_w1_h[NLAYER * FFDIM * DMODEL];
__device__ __nv_bfloat16 g_w1_l[NLAYER * FFDIM * DMODEL];
__device__ __nv_bfloat16 g_w2_h[NLAYER * DMODEL * FFDIM];
__device__ __nv_bfloat16 g_w2_l[NLAYER * DMODEL * FFDIM];

// -------------------- helpers --------------------
__device__ __forceinline__ void cp_async16(uint32_t smem, const void* g) {
    asm volatile("cp.async.cg.shared.global [%0], [%1], 16;\n" :: "r"(smem), "l"(g));
}
__device__ __forceinline__ void cp_commit() {
    asm volatile("cp.async.commit_group;\n" ::: "memory");
}
__device__ __forceinline__ void cp_wait0() {
    asm volatile("cp.async.wait_group 0;\n" ::: "memory");
}
__device__ __forceinline__ uint32_t smem_u32(const void* p) {
    return (uint32_t)__cvta_generic_to_shared(p);
}
__device__ __forceinline__ void split2(float v, __nv_bfloat16& h, __nv_bfloat16& l) {
    h = __float2bfloat16(v);
    l = __float2bfloat16(v - __bfloat162float(h));
}
__device__ __forceinline__ void mma_bf16(float* d, const uint32_t* a, const uint32_t* b) {
    asm volatile(
        "mma.sync.aligned.m16n8k16.row.col.f32.bf16.bf16.f32 "
        "{%0,%1,%2,%3}, {%4,%5,%6,%7}, {%8,%9}, {%0,%1,%2,%3};\n"
        : "+f"(d[0]), "+f"(d[1]), "+f"(d[2]), "+f"(d[3])
        : "r"(a[0]), "r"(a[1]), "r"(a[2]), "r"(a[3]),
          "r"(b[0]), "r"(b[1]));
}

// -------------------- copy --------------------
__global__ void copy_kernel(const float4* __restrict__ in, float4* __restrict__ out, int n4) {
    int i = blockIdx.x * blockDim.x + threadIdx.x;
    if (i < n4) out[i] = in[i];
}

// -------------------- weight split (fp32 -> hi/lo bf16 planes) --------------------
__global__ void split_kernel(const float4* __restrict__ in,
                             __nv_bfloat162* __restrict__ hi,
                             __nv_bfloat162* __restrict__ lo, int n4) {
    int i = blockIdx.x * blockDim.x + threadIdx.x;
    if (i >= n4) return;
    float4 v = in[i];
    __nv_bfloat16 h0, l0, h1, l1, h2, l2, h3, l3;
    split2(v.x, h0, l0); split2(v.y, h1, l1);
    split2(v.z, h2, l2); split2(v.w, h3, l3);
    __nv_bfloat162 ph0; ph0.x = h0; ph0.y = h1;
    __nv_bfloat162 ph1; ph1.x = h2; ph1.y = h3;
    __nv_bfloat162 pl0; pl0.x = l0; pl0.y = l1;
    __nv_bfloat162 pl1; pl1.x = l2; pl1.y = l3;
    hi[i * 2 + 0] = ph0; hi[i * 2 + 1] = ph1;
    lo[i * 2 + 0] = pl0; lo[i * 2 + 1] = pl1;
}

// -------------------- layernorm (fp32 out — final) --------------------
__global__ void __launch_bounds__(256) ln_kernel(
    const float* __restrict__ in, const float* __restrict__ w,
    const float* __restrict__ b, float* __restrict__ out)
{
    int row = blockIdx.x;
    int tid = threadIdx.x;
    const float4* ip = (const float4*)(in + (size_t)row * DMODEL);
    float4 v = ip[tid];
    float s  = v.x + v.y + v.z + v.w;
    float sq = v.x * v.x + v.y * v.y + v.z * v.z + v.w * v.w;
    #pragma unroll
    for (int o = 16; o > 0; o >>= 1) {
        s  += __shfl_xor_sync(0xffffffffu, s,  o);
        sq += __shfl_xor_sync(0xffffffffu, sq, o);
    }
    __shared__ float reds[8], redq[8];
    int lane = tid & 31, wid = tid >> 5;
    if (lane == 0) { reds[wid] = s; redq[wid] = sq; }
    __syncthreads();
    float ts = 0.f, tq = 0.f;
    #pragma unroll
    for (int i = 0; i < 8; i++) { ts += reds[i]; tq += redq[i]; }
    float mean = ts * (1.0f / DMODEL);
    float var  = tq * (1.0f / DMODEL) - mean * mean;
    float rstd = rsqrtf(var + 1e-5f);
    float4 wv = ((const float4*)w)[tid];
    float4 bv = ((const float4*)b)[tid];
    float4 r;
    r.x = (v.x - mean) * rstd * wv.x + bv.x;
    r.y = (v.y - mean) * rstd * wv.y + bv.y;
    r.z = (v.z - mean) * rstd * wv.z + bv.z;
    r.w = (v.w - mean) * rstd * wv.w + bv.w;
    ((float4*)(out + (size_t)row * DMODEL))[tid] = r;
}

// -------------------- layernorm (dual-bf16 out) --------------------
__global__ void __launch_bounds__(256) ln_dual_kernel(
    const float* __restrict__ in, const float* __restrict__ w,
    const float* __restrict__ b,
    __nv_bfloat16* __restrict__ oh, __nv_bfloat16* __restrict__ ol)
{
    int row = blockIdx.x;
    int tid = threadIdx.x;
    const float4* ip = (const float4*)(in + (size_t)row * DMODEL);
    float4 v = ip[tid];
    float s  = v.x + v.y + v.z + v.w;
    float sq = v.x * v.x + v.y * v.y + v.z * v.z + v.w * v.w;
    #pragma unroll
    for (int o = 16; o > 0; o >>= 1) {
        s  += __shfl_xor_sync(0xffffffffu, s,  o);
        sq += __shfl_xor_sync(0xffffffffu, sq, o);
    }
    __shared__ float reds[8], redq[8];
    int lane = tid & 31, wid = tid >> 5;
    if (lane == 0) { reds[wid] = s; redq[wid] = sq; }
    __syncthreads();
    float ts = 0.f, tq = 0.f;
    #pragma unroll
    for (int i = 0; i < 8; i++) { ts += reds[i]; tq += redq[i]; }
    float mean = ts * (1.0f / DMODEL);
    float var  = tq * (1.0f / DMODEL) - mean * mean;
    float rstd = rsqrtf(var + 1e-5f);
    float4 wv = ((const float4*)w)[tid];
    float4 bv = ((const float4*)b)[tid];
    float r0 = (v.x - mean) * rstd * wv.x + bv.x;
    float r1 = (v.y - mean) * rstd * wv.y + bv.y;
    float r2 = (v.z - mean) * rstd * wv.z + bv.z;
    float r3 = (v.w - mean) * rstd * wv.w + bv.w;
    __nv_bfloat16 h0, l0, h1, l1, h2, l2, h3, l3;
    split2(r0, h0, l0); split2(r1, h1, l1); split2(r2, h2, l2); split2(r3, h3, l3);
    size_t base = (size_t)row * DMODEL + tid * 4;
    __nv_bfloat162 ph0; ph0.x = h0; ph0.y = h1;
    __nv_bfloat162 ph1; ph1.x = h2; ph1.y = h3;
    __nv_bfloat162 pl0; pl0.x = l0; pl0.y = l1;
    __nv_bfloat162 pl1; pl1.x = l2; pl1.y = l3;
    *(__nv_bfloat162*)(oh + base)     = ph0;
    *(__nv_bfloat162*)(oh + base + 2) = ph1;
    *(__nv_bfloat162*)(ol + base)     = pl0;
    *(__nv_bfloat162*)(ol + base + 2) = pl1;
}

// -------------------- bf16 split-3 tensor-core GEMM (mma.sync m16n8k16) --------------------
// C[M,N] = A[M,K] @ W[N,K]^T + bias; A,W as hi/lo bf16 planes (K-major).
// Block 256(M) x 128(N), BK=32, 256 threads = 8 warps (4M x 2N), warp tile 64x64.
// Terms: Ah*Wh + Ah*Wl + Al*Wh. Smem pitch 40 bf16 (80B) -> conflict-free LDS.32.
// EPI: 0 = bias -> fp32 ; 1 = bias+GELU -> dual-bf16 ; 2 = bias+residual -> fp32
#define GPITCH 40                             // bf16 elements per row in smem
#define A_ELE (256 * GPITCH)                  // per A plane per stage
#define W_ELE (128 * GPITCH)
#define STG_ELE (2 * A_ELE + 2 * W_ELE)       // Ah, Al, Wh, Wl
#define GEMM_SMEM (2 * STG_ELE * 2)           // bytes (2 stages, 2B/elem)

template <int EPI>
__global__ void __launch_bounds__(256, 1) gemm_bf16(
    const __nv_bfloat16* __restrict__ Ah, const __nv_bfloat16* __restrict__ Al,
    const __nv_bfloat16* __restrict__ Wh, const __nv_bfloat16* __restrict__ Wl,
    const float* __restrict__ bias, const float* __restrict__ res,
    float* __restrict__ Cf, __nv_bfloat16* __restrict__ Ch, __nv_bfloat16* __restrict__ Cl,
    int M, int N, int K)
{
    extern __shared__ __nv_bfloat16 smem[];
    uint32_t sbase = smem_u32(smem);

    int tid  = threadIdx.x;
    int lane = tid & 31;
    int wid  = tid >> 5;
    int warpM = (wid >> 1) * 64;      // 0,64,128,192
    int warpN = (wid & 1) * 64;       // 0,64
    int m0 = blockIdx.y * 256;
    int n0 = blockIdx.x * 128;

    int gr = lane >> 2;               // 0..7
    int gc = lane & 3;                // 0..3

    float acc[4][8][4];
    #pragma unroll
    for (int i = 0; i < 4; i++)
        #pragma unroll
        for (int j = 0; j < 8; j++)
            #pragma unroll
            for (int c = 0; c < 4; c++) acc[i][j][c] = 0.f;

    int KT = K >> 5;   // 32-K chunks

    // stage layout (bf16 elems): [Ah][Al][Wh][Wl]
    auto load_chunk = [&](int kt) {
        uint32_t sb = sbase + (uint32_t)(kt & 1) * STG_ELE * 2;
        int k0 = kt << 5;
        #pragma unroll
        for (int i = 0; i < 4; i++) {
            int idx = tid + i * 256;          // 0..1023
            int row = idx >> 2;               // 0..255
            int k16 = idx & 3;                // 16B slot (8 bf16)
            uint32_t so = (uint32_t)(row * 80 + k16 * 16);
            size_t ga = (size_t)(m0 + row) * K + k0 + k16 * 8;
            cp_async16(sb + so, Ah + ga);
            cp_async16(sb + A_ELE * 2 + so, Al + ga);
        }
        #pragma unroll
        for (int i = 0; i < 2; i++) {
            int idx = tid + i * 256;          // 0..511
            int row = idx >> 2;               // 0..127
            int k16 = idx & 3;
            uint32_t so = (uint32_t)(row * 80 + k16 * 16);
            size_t gw = (size_t)(n0 + row) * K + k0 + k16 * 8;
            cp_async16(sb + 2 * A_ELE * 2 + so, Wh + gw);
            cp_async16(sb + (2 * A_ELE + W_ELE) * 2 + so, Wl + gw);
        }
        cp_commit();
    };

    load_chunk(0);

    for (int kt = 0; kt < KT; kt++) {
        cp_wait0();
        __syncthreads();
        if (kt + 1 < KT) load_chunk(kt + 1);

        const char* stg = (const char*)smem + (size_t)(kt & 1) * STG_ELE * 2;
        const char* sAh = stg;
        const char* sAl = stg + A_ELE * 2;
        const char* sWh = stg + 2 * A_ELE * 2;
        const char* sWl = stg + (2 * A_ELE + W_ELE) * 2;

        #pragma unroll
        for (int ks = 0; ks < 2; ks++) {
            int kb = ks * 16;                 // k offset within chunk
            int kby = kb * 2 + gc * 4;        // byte offset of this thread's k-pair
            uint32_t ah[4][4], al[4][4], bh[8][2], bl[8][2];
            #pragma unroll
            for (int mt = 0; mt < 4; mt++) {
                int r = warpM + mt * 16 + gr;
                const char* p0 = sAh + r * 80 + kby;
                const char* p1 = sAh + (r + 8) * 80 + kby;
                ah[mt][0] = *(const uint32_t*)p0;
                ah[mt][1] = *(const uint32_t*)p1;
                ah[mt][2] = *(const uint32_t*)(p0 + 16);
                ah[mt][3] = *(const uint32_t*)(p1 + 16);
                const char* q0 = sAl + r * 80 + kby;
                const char* q1 = sAl + (r + 8) * 80 + kby;
                al[mt][0] = *(const uint32_t*)q0;
                al[mt][1] = *(const uint32_t*)q1;
                al[mt][2] = *(const uint32_t*)(q0 + 16);
                al[mt][3] = *(const uint32_t*)(q1 + 16);
            }
            #pragma unroll
            for (int nt = 0; nt < 8; nt++) {
                int c = warpN + nt * 8 + gr;
                const char* p = sWh + c * 80 + kby;
                bh[nt][0] = *(const uint32_t*)p;
                bh[nt][1] = *(const uint32_t*)(p + 16);
                const char* q = sWl + c * 80 + kby;
                bl[nt][0] = *(const uint32_t*)q;
                bl[nt][1] = *(const uint32_t*)(q + 16);
            }
            #pragma unroll
            for (int mt = 0; mt < 4; mt++)
                #pragma unroll
                for (int nt = 0; nt < 8; nt++) {
                    mma_bf16(acc[mt][nt], ah[mt], bh[nt]);
                    mma_bf16(acc[mt][nt], ah[mt], bl[nt]);
                    mma_bf16(acc[mt][nt], al[mt], bh[nt]);
                }
        }
        __syncthreads();
    }

    // ---- epilogue ----
    #pragma unroll
    for (int mt = 0; mt < 4; mt++) {
        int r0 = m0 + warpM + mt * 16 + gr;
        #pragma unroll
        for (int nt = 0; nt < 8; nt++) {
            int col = n0 + warpN + nt * 8 + 2 * gc;
            float b0 = bias[col], b1 = bias[col + 1];
            #pragma unroll
            for (int half = 0; half < 2; half++) {
                int row = r0 + half * 8;
                float v0 = acc[mt][nt][2 * half + 0] + b0;
                float v1 = acc[mt][nt][2 * half + 1] + b1;
                if (EPI == 1) {
                    v0 = 0.5f * v0 * (1.0f + erff(v0 * 0.70710678118654752f));
                    v1 = 0.5f * v1 * (1.0f + erff(v1 * 0.70710678118654752f));
                    __nv_bfloat16 h0, l0, h1, l1;
                    split2(v0, h0, l0); split2(v1, h1, l1);
                    __nv_bfloat162 ph; ph.x = h0; ph.y = h1;
                    __nv_bfloat162 pl; pl.x = l0; pl.y = l1;
                    size_t base = (size_t)row * N + col;
                    *(__nv_bfloat162*)(Ch + base) = ph;
                    *(__nv_bfloat162*)(Cl + base) = pl;
                } else {
                    if (EPI == 2) {
                        const float2 rv = *(const float2*)(res + (size_t)row * N + col);
                        v0 += rv.x; v1 += rv.y;
                    }
                    float2 o2; o2.x = v0; o2.y = v1;
                    *(float2*)(Cf + (size_t)row * N + col) = o2;
                }
            }
        }
    }
}

// -------------------- flash attention (fp32, causal + ALiBi, dual-bf16 out) -----------
__global__ void __launch_bounds__(128) attn_kernel(
    const float* __restrict__ qkv,
    __nv_bfloat16* __restrict__ oh, __nv_bfloat16* __restrict__ ol)
{
    int b    = blockIdx.z;
    int h    = blockIdx.y;
    int qblk = blockIdx.x;
    int qi   = qblk * 128 + threadIdx.x;

    __shared__ float Ks[32][64];
    __shared__ float Vs[32][64];

    float q[64];
    {
        const float4* qp = (const float4*)(qkv + ((size_t)(b * TSEQ + qi)) * QKVDIM + h * HEADDIM);
        #pragma unroll
        for (int i = 0; i < 16; i++) {
            float4 t4 = qp[i];
            q[4*i+0] = t4.x; q[4*i+1] = t4.y; q[4*i+2] = t4.z; q[4*i+3] = t4.w;
        }
    }

    float o[64];
    #pragma unroll
    for (int d = 0; d < 64; d++) o[d] = 0.f;
    float m = -INFINITY, l = 0.f;
    float slope = exp2f(-0.5f * (float)(h + 1));

    int ntiles = qblk * 4 + 4;

    for (int t = 0; t < ntiles; t++) {
        int kbase = t * 32;
        __syncthreads();
        #pragma unroll
        for (int i = 0; i < 4; i++) {
            int f = threadIdx.x + i * 128;
            int r = f >> 4;
            int c = (f & 15) * 4;
            const float* kp = qkv + ((size_t)(b * TSEQ + kbase + r)) * QKVDIM + DMODEL + h * HEADDIM + c;
            *(float4*)&Ks[r][c] = *(const float4*)kp;
            *(float4*)&Vs[r][c] = *(const float4*)(kp + DMODEL);
        }
        __syncthreads();

        float s[32];
        #pragma unroll
        for (int j = 0; j < 32; j++) {
            float acc2 = 0.f;
            #pragma unroll
            for (int d4 = 0; d4 < 16; d4++) {
                float4 kv = *(const float4*)&Ks[j][d4 * 4];
                acc2 += q[4*d4+0] * kv.x + q[4*d4+1] * kv.y
                      + q[4*d4+2] * kv.z + q[4*d4+3] * kv.w;
            }
            int kpos = kbase + j;
            s[j] = (kpos <= qi) ? (0.125f * acc2 + slope * (float)(kpos - qi)) : -INFINITY;
        }

        float tm = m;
        #pragma unroll
        for (int j = 0; j < 32; j++) tm = fmaxf(tm, s[j]);
        float corr = __expf(m - tm);
        m = tm;
        l *= corr;
        #pragma unroll
        for (int d = 0; d < 64; d++) o[d] *= corr;
        #pragma unroll
        for (int j = 0; j < 32; j++) {
            float p = __expf(s[j] - m);
            l += p;
            #pragma unroll
            for (int d4 = 0; d4 < 16; d4++) {
                float4 vv = *(const float4*)&Vs[j][d4 * 4];
                o[4*d4+0] += p * vv.x; o[4*d4+1] += p * vv.y;
                o[4*d4+2] += p * vv.z; o[4*d4+3] += p * vv.w;
            }
        }
    }

    float inv = 1.0f / l;
    size_t base = ((size_t)(b * TSEQ + qi)) * DMODEL + h * HEADDIM;
    #pragma unroll
    for (int i = 0; i < 32; i++) {
        float v0 = o[2*i+0] * inv;
        float v1 = o[2*i+1] * inv;
        __nv_bfloat16 h0, l0, h1, l1;
        split2(v0, h0, l0); split2(v1, h1, l1);
        __nv_bfloat162 ph; ph.x = h0; ph.y = h1;
        __nv_bfloat162 pl; pl.x = l0; pl.y = l1;
        *(__nv_bfloat162*)(oh + base + 2 * i) = ph;
        *(__nv_bfloat162*)(ol + base + 2 * i) = pl;
    }
}

// -------------------- launch --------------------
extern "C" void kernel_launch(void* const* d_in, const int* in_sizes, int n_in,
                              void* d_out, int out_size)
{
    const float* x        = (const float*)d_in[0];
    const float* in_w     = (const float*)d_in[1];
    const float* in_b     = (const float*)d_in[2];
    const float* out_w    = (const float*)d_in[3];
    const float* out_b    = (const float*)d_in[4];
    const float* f1_w     = (const float*)d_in[5];
    const float* f1_b     = (const float*)d_in[6];
    const float* f2_w     = (const float*)d_in[7];
    const float* f2_b     = (const float*)d_in[8];
    const float* ln1_w    = (const float*)d_in[9];
    const float* ln1_b    = (const float*)d_in[10];
    const float* ln2_w    = (const float*)d_in[11];
    const float* ln2_b    = (const float*)d_in[12];
    const float* final_w  = (const float*)d_in[13];
    const float* final_b  = (const float*)d_in[14];

    float *x_, *qkv_;
    __nv_bfloat16 *xnh, *xnl, *atth, *attl, *hh, *hl;
    __nv_bfloat16 *wih, *wil, *woh, *wol, *w1h, *w1l, *w2h, *w2l;
    cudaGetSymbolAddress((void**)&x_,   g_x);
    cudaGetSymbolAddress((void**)&qkv_, g_qkv);
    cudaGetSymbolAddress((void**)&xnh,  g_xn_h);
    cudaGetSymbolAddress((void**)&xnl,  g_xn_l);
    cudaGetSymbolAddress((void**)&atth, g_att_h);
    cudaGetSymbolAddress((void**)&attl, g_att_l);
    cudaGetSymbolAddress((void**)&hh,   g_h_h);
    cudaGetSymbolAddress((void**)&hl,   g_h_l);
    cudaGetSymbolAddress((void**)&wih,  g_wi_h);
    cudaGetSymbolAddress((void**)&wil,  g_wi_l);
    cudaGetSymbolAddress((void**)&woh,  g_wo_h);
    cudaGetSymbolAddress((void**)&wol,  g_wo_l);
    cudaGetSymbolAddress((void**)&w1h,  g_w1_h);
    cudaGetSymbolAddress((void**)&w1l,  g_w1_l);
    cudaGetSymbolAddress((void**)&w2h,  g_w2_h);
    cudaGetSymbolAddress((void**)&w2l,  g_w2_l);

    cudaFuncSetAttribute(gemm_bf16<0>, cudaFuncAttributeMaxDynamicSharedMemorySize, GEMM_SMEM);
    cudaFuncSetAttribute(gemm_bf16<1>, cudaFuncAttributeMaxDynamicSharedMemorySize, GEMM_SMEM);
    cudaFuncSetAttribute(gemm_bf16<2>, cudaFuncAttributeMaxDynamicSharedMemorySize, GEMM_SMEM);

    // split all weights into hi/lo bf16 planes
    {
        int n4;
        n4 = NLAYER * QKVDIM * DMODEL / 4;
        split_kernel<<<(n4 + 255) / 256, 256>>>((const float4*)in_w,
            (__nv_bfloat162*)wih, (__nv_bfloat162*)wil, n4);
        n4 = NLAYER * DMODEL * DMODEL / 4;
        split_kernel<<<(n4 + 255) / 256, 256>>>((const float4*)out_w,
            (__nv_bfloat162*)woh, (__nv_bfloat162*)wol, n4);
        n4 = NLAYER * FFDIM * DMODEL / 4;
        split_kernel<<<(n4 + 255) / 256, 256>>>((const float4*)f1_w,
            (__nv_bfloat162*)w1h, (__nv_bfloat162*)w1l, n4);
        n4 = NLAYER * DMODEL * FFDIM / 4;
        split_kernel<<<(n4 + 255) / 256, 256>>>((const float4*)f2_w,
            (__nv_bfloat162*)w2h, (__nv_bfloat162*)w2l, n4);
    }

    // residual stream init
    {
        int n4 = ROWS * DMODEL / 4;
        copy_kernel<<<(n4 + 255) / 256, 256>>>((const float4*)x, (float4*)x_, n4);
    }

    dim3 blk256(256);
    for (int i = 0; i < NLAYER; i++) {
        __nv_bfloat16* iwh = wih + (size_t)i * QKVDIM * DMODEL;
        __nv_bfloat16* iwl = wil + (size_t)i * QKVDIM * DMODEL;
        __nv_bfloat16* owh = woh + (size_t)i * DMODEL * DMODEL;
        __nv_bfloat16* owl = wol + (size_t)i * DMODEL * DMODEL;
        __nv_bfloat16* f1h = w1h + (size_t)i * FFDIM * DMODEL;
        __nv_bfloat16* f1l = w1l + (size_t)i * FFDIM * DMODEL;
        __nv_bfloat16* f2h = w2h + (size_t)i * DMODEL * FFDIM;
        __nv_bfloat16* f2l = w2l + (size_t)i * DMODEL * FFDIM;
        const float* ib = in_b  + (size_t)i * QKVDIM;
        const float* ob = out_b + (size_t)i * DMODEL;
        const float* b1 = f1_b  + (size_t)i * FFDIM;
        const float* b2 = f2_b  + (size_t)i * DMODEL;

        // LN1 -> dual xn
        ln_dual_kernel<<<ROWS, blk256>>>(x_, ln1_w + i * DMODEL, ln1_b + i * DMODEL, xnh, xnl);
        // QKV projection (fp32 out)
        gemm_bf16<0><<<dim3(QKVDIM / 128, ROWS / 256), blk256, GEMM_SMEM>>>(
            xnh, xnl, iwh, iwl, ib, nullptr, qkv_, nullptr, nullptr, ROWS, QKVDIM, DMODEL);
        // attention -> dual att
        attn_kernel<<<dim3(TSEQ / 128, NHEAD, BATCH), 128>>>(qkv_, atth, attl);
        // out projection + residual -> x (fp32)
        gemm_bf16<2><<<dim3(DMODEL / 128, ROWS / 256), blk256, GEMM_SMEM>>>(
            atth, attl, owh, owl, ob, x_, x_, nullptr, nullptr, ROWS, DMODEL, DMODEL);
        // LN2 -> dual xn
        ln_dual_kernel<<<ROWS, blk256>>>(x_, ln2_w + i * DMODEL, ln2_b + i * DMODEL, xnh, xnl);
        // FFN1 + GELU -> dual h
        gemm_bf16<1><<<dim3(FFDIM / 128, ROWS / 256), blk256, GEMM_SMEM>>>(
            xnh, xnl, f1h, f1l, b1, nullptr, nullptr, hh, hl, ROWS, FFDIM, DMODEL);
        // FFN2 + residual -> x (fp32)
        gemm_bf16<2><<<dim3(DMODEL / 128, ROWS / 256), blk256, GEMM_SMEM>>>(
            hh, hl, f2h, f2l, b2, x_, x_, nullptr, nullptr, ROWS, DMODEL, FFDIM);
    }
    ln_kernel<<<ROWS, blk256>>>(x_, final_w, final_b, (float*)d_out);
}

// round 9
// speedup vs baseline: 1.6917x; 1.6917x over previous
#include <cuda_runtime.h>
#include <cuda_bf16.h>
#include <math.h>
#include <stdint.h>

// Problem constants
#define TSEQ    2048
#define BATCH   2
#define DMODEL  1024
#define NHEAD   16
#define HEADDIM 64
#define FFDIM   4096
#define NLAYER  4
#define ROWS    (BATCH * TSEQ)          // 4096
#define QKVDIM  (3 * DMODEL)            // 3072

// -------------------- scratch (allocation-free) --------------------
__device__ float g_x  [ROWS * DMODEL];          // residual stream (fp32)
__device__ float g_qkv[ROWS * QKVDIM];          // qkv projection (fp32)
// dual-bf16 activation planes
__device__ __nv_bfloat16 g_xn_h [ROWS * DMODEL];
__device__ __nv_bfloat16 g_xn_l [ROWS * DMODEL];
__device__ __nv_bfloat16 g_att_h[ROWS * DMODEL];
__device__ __nv_bfloat16 g_att_l[ROWS * DMODEL];
__device__ __nv_bfloat16 g_h_h  [ROWS * FFDIM];
__device__ __nv_bfloat16 g_h_l  [ROWS * FFDIM];
// dual-bf16 weight planes (split per launch)
__device__ __nv_bfloat16 g_wi_h[NLAYER * QKVDIM * DMODEL];
__device__ __nv_bfloat16 g_wi_l[NLAYER * QKVDIM * DMODEL];
__device__ __nv_bfloat16 g_wo_h[NLAYER * DMODEL * DMODEL];
__device__ __nv_bfloat16 g_wo_l[NLAYER * DMODEL * DMODEL];
__device__ __nv_bfloat16 g_w1_h[NLAYER * FFDIM * DMODEL];
__device__ __nv_bfloat16 g_w1_l[NLAYER * FFDIM * DMODEL];
__device__ __nv_bfloat16 g_w2_h[NLAYER * DMODEL * FFDIM];
__device__ __nv_bfloat16 g_w2_l[NLAYER * DMODEL * FFDIM];

// -------------------- helpers --------------------
__device__ __forceinline__ void cp_async16(uint32_t smem, const void* g) {
    asm volatile("cp.async.cg.shared.global [%0], [%1], 16;\n" :: "r"(smem), "l"(g));
}
__device__ __forceinline__ void cp_commit() {
    asm volatile("cp.async.commit_group;\n" ::: "memory");
}
__device__ __forceinline__ void cp_wait0() {
    asm volatile("cp.async.wait_group 0;\n" ::: "memory");
}
__device__ __forceinline__ uint32_t smem_u32(const void* p) {
    return (uint32_t)__cvta_generic_to_shared(p);
}
__device__ __forceinline__ void split2(float v, __nv_bfloat16& h, __nv_bfloat16& l) {
    h = __float2bfloat16(v);
    l = __float2bfloat16(v - __bfloat162float(h));
}
__device__ __forceinline__ void mma_bf16(float* d, const uint32_t* a, const uint32_t* b) {
    asm volatile(
        "mma.sync.aligned.m16n8k16.row.col.f32.bf16.bf16.f32 "
        "{%0,%1,%2,%3}, {%4,%5,%6,%7}, {%8,%9}, {%0,%1,%2,%3};\n"
        : "+f"(d[0]), "+f"(d[1]), "+f"(d[2]), "+f"(d[3])
        : "r"(a[0]), "r"(a[1]), "r"(a[2]), "r"(a[3]),
          "r"(b[0]), "r"(b[1]));
}

// -------------------- copy --------------------
__global__ void copy_kernel(const float4* __restrict__ in, float4* __restrict__ out, int n4) {
    int i = blockIdx.x * blockDim.x + threadIdx.x;
    if (i < n4) out[i] = in[i];
}

// -------------------- weight split (fp32 -> hi/lo bf16 planes) --------------------
__global__ void split_kernel(const float4* __restrict__ in,
                             __nv_bfloat162* __restrict__ hi,
                             __nv_bfloat162* __restrict__ lo, int n4) {
    int i = blockIdx.x * blockDim.x + threadIdx.x;
    if (i >= n4) return;
    float4 v = in[i];
    __nv_bfloat16 h0, l0, h1, l1, h2, l2, h3, l3;
    split2(v.x, h0, l0); split2(v.y, h1, l1);
    split2(v.z, h2, l2); split2(v.w, h3, l3);
    __nv_bfloat162 ph0; ph0.x = h0; ph0.y = h1;
    __nv_bfloat162 ph1; ph1.x = h2; ph1.y = h3;
    __nv_bfloat162 pl0; pl0.x = l0; pl0.y = l1;
    __nv_bfloat162 pl1; pl1.x = l2; pl1.y = l3;
    hi[i * 2 + 0] = ph0; hi[i * 2 + 1] = ph1;
    lo[i * 2 + 0] = pl0; lo[i * 2 + 1] = pl1;
}

// -------------------- layernorm (fp32 out — final) --------------------
__global__ void __launch_bounds__(256) ln_kernel(
    const float* __restrict__ in, const float* __restrict__ w,
    const float* __restrict__ b, float* __restrict__ out)
{
    int row = blockIdx.x;
    int tid = threadIdx.x;
    const float4* ip = (const float4*)(in + (size_t)row * DMODEL);
    float4 v = ip[tid];
    float s  = v.x + v.y + v.z + v.w;
    float sq = v.x * v.x + v.y * v.y + v.z * v.z + v.w * v.w;
    #pragma unroll
    for (int o = 16; o > 0; o >>= 1) {
        s  += __shfl_xor_sync(0xffffffffu, s,  o);
        sq += __shfl_xor_sync(0xffffffffu, sq, o);
    }
    __shared__ float reds[8], redq[8];
    int lane = tid & 31, wid = tid >> 5;
    if (lane == 0) { reds[wid] = s; redq[wid] = sq; }
    __syncthreads();
    float ts = 0.f, tq = 0.f;
    #pragma unroll
    for (int i = 0; i < 8; i++) { ts += reds[i]; tq += redq[i]; }
    float mean = ts * (1.0f / DMODEL);
    float var  = tq * (1.0f / DMODEL) - mean * mean;
    float rstd = rsqrtf(var + 1e-5f);
    float4 wv = ((const float4*)w)[tid];
    float4 bv = ((const float4*)b)[tid];
    float4 r;
    r.x = (v.x - mean) * rstd * wv.x + bv.x;
    r.y = (v.y - mean) * rstd * wv.y + bv.y;
    r.z = (v.z - mean) * rstd * wv.z + bv.z;
    r.w = (v.w - mean) * rstd * wv.w + bv.w;
    ((float4*)(out + (size_t)row * DMODEL))[tid] = r;
}

// -------------------- layernorm (dual-bf16 out) --------------------
__global__ void __launch_bounds__(256) ln_dual_kernel(
    const float* __restrict__ in, const float* __restrict__ w,
    const float* __restrict__ b,
    __nv_bfloat16* __restrict__ oh, __nv_bfloat16* __restrict__ ol)
{
    int row = blockIdx.x;
    int tid = threadIdx.x;
    const float4* ip = (const float4*)(in + (size_t)row * DMODEL);
    float4 v = ip[tid];
    float s  = v.x + v.y + v.z + v.w;
    float sq = v.x * v.x + v.y * v.y + v.z * v.z + v.w * v.w;
    #pragma unroll
    for (int o = 16; o > 0; o >>= 1) {
        s  += __shfl_xor_sync(0xffffffffu, s,  o);
        sq += __shfl_xor_sync(0xffffffffu, sq, o);
    }
    __shared__ float reds[8], redq[8];
    int lane = tid & 31, wid = tid >> 5;
    if (lane == 0) { reds[wid] = s; redq[wid] = sq; }
    __syncthreads();
    float ts = 0.f, tq = 0.f;
    #pragma unroll
    for (int i = 0; i < 8; i++) { ts += reds[i]; tq += redq[i]; }
    float mean = ts * (1.0f / DMODEL);
    float var  = tq * (1.0f / DMODEL) - mean * mean;
    float rstd = rsqrtf(var + 1e-5f);
    float4 wv = ((const float4*)w)[tid];
    float4 bv = ((const float4*)b)[tid];
    float r0 = (v.x - mean) * rstd * wv.x + bv.x;
    float r1 = (v.y - mean) * rstd * wv.y + bv.y;
    float r2 = (v.z - mean) * rstd * wv.z + bv.z;
    float r3 = (v.w - mean) * rstd * wv.w + bv.w;
    __nv_bfloat16 h0, l0, h1, l1, h2, l2, h3, l3;
    split2(r0, h0, l0); split2(r1, h1, l1); split2(r2, h2, l2); split2(r3, h3, l3);
    size_t base = (size_t)row * DMODEL + tid * 4;
    __nv_bfloat162 ph0; ph0.x = h0; ph0.y = h1;
    __nv_bfloat162 ph1; ph1.x = h2; ph1.y = h3;
    __nv_bfloat162 pl0; pl0.x = l0; pl0.y = l1;
    __nv_bfloat162 pl1; pl1.x = l2; pl1.y = l3;
    *(__nv_bfloat162*)(oh + base)     = ph0;
    *(__nv_bfloat162*)(oh + base + 2) = ph1;
    *(__nv_bfloat162*)(ol + base)     = pl0;
    *(__nv_bfloat162*)(ol + base + 2) = pl1;
}

// -------------------- bf16 split-3 tensor-core GEMM (mma.sync m16n8k16) --------------------
// C[M,N] = A[M,K] @ W[N,K]^T + bias; A,W as hi/lo bf16 planes (K-major).
// Block 128(M) x 128(N), BK=32, 256 threads = 8 warps (4M x 2N), warp tile 32x64.
// Terms: Ah*Wh + Ah*Wl + Al*Wh. A-frags cached per ks; B-frags streamed per nt
// (register budget ~110 -> launch_bounds(256,2), 2 CTAs/SM).
// Smem pitch 40 bf16 (80B) -> conflict-free LDS.32.
// EPI: 0 = bias -> fp32 ; 1 = bias+GELU -> dual-bf16 ; 2 = bias+residual -> fp32
#define GPITCH 40                             // bf16 elements per row in smem
#define A_ELE (128 * GPITCH)                  // per A plane per stage
#define W_ELE (128 * GPITCH)
#define STG_ELE (2 * A_ELE + 2 * W_ELE)       // Ah, Al, Wh, Wl
#define GEMM_SMEM (2 * STG_ELE * 2)           // bytes (2 stages, 2B/elem) = 81920

template <int EPI>
__global__ void __launch_bounds__(256, 2) gemm_bf16(
    const __nv_bfloat16* __restrict__ Ah, const __nv_bfloat16* __restrict__ Al,
    const __nv_bfloat16* __restrict__ Wh, const __nv_bfloat16* __restrict__ Wl,
    const float* __restrict__ bias, const float* __restrict__ res,
    float* __restrict__ Cf, __nv_bfloat16* __restrict__ Ch, __nv_bfloat16* __restrict__ Cl,
    int M, int N, int K)
{
    extern __shared__ __nv_bfloat16 smem[];
    uint32_t sbase = smem_u32(smem);

    int tid  = threadIdx.x;
    int lane = tid & 31;
    int wid  = tid >> 5;
    int warpM = (wid >> 1) * 32;      // 0,32,64,96
    int warpN = (wid & 1) * 64;       // 0,64
    int m0 = blockIdx.y * 128;
    int n0 = blockIdx.x * 128;

    int gr = lane >> 2;               // 0..7
    int gc = lane & 3;                // 0..3

    float acc[2][8][4];
    #pragma unroll
    for (int i = 0; i < 2; i++)
        #pragma unroll
        for (int j = 0; j < 8; j++)
            #pragma unroll
            for (int c = 0; c < 4; c++) acc[i][j][c] = 0.f;

    int KT = K >> 5;   // 32-K chunks

    // stage layout (bf16 elems): [Ah][Al][Wh][Wl], 128 rows x 40 pitch each
    auto load_chunk = [&](int kt) {
        uint32_t sb = sbase + (uint32_t)(kt & 1) * STG_ELE * 2;
        int k0 = kt << 5;
        #pragma unroll
        for (int i = 0; i < 2; i++) {
            int idx = tid + i * 256;          // 0..511
            int row = idx >> 2;               // 0..127
            int k16 = idx & 3;                // 16B slot (8 bf16)
            uint32_t so = (uint32_t)(row * 80 + k16 * 16);
            size_t ga = (size_t)(m0 + row) * K + k0 + k16 * 8;
            size_t gw = (size_t)(n0 + row) * K + k0 + k16 * 8;
            cp_async16(sb + so, Ah + ga);
            cp_async16(sb + A_ELE * 2 + so, Al + ga);
            cp_async16(sb + 2 * A_ELE * 2 + so, Wh + gw);
            cp_async16(sb + (2 * A_ELE + W_ELE) * 2 + so, Wl + gw);
        }
        cp_commit();
    };

    load_chunk(0);

    for (int kt = 0; kt < KT; kt++) {
        cp_wait0();
        __syncthreads();
        if (kt + 1 < KT) load_chunk(kt + 1);

        const char* stg = (const char*)smem + (size_t)(kt & 1) * STG_ELE * 2;
        const char* sAh = stg;
        const char* sAl = stg + A_ELE * 2;
        const char* sWh = stg + 2 * A_ELE * 2;
        const char* sWl = stg + (2 * A_ELE + W_ELE) * 2;

        #pragma unroll
        for (int ks = 0; ks < 2; ks++) {
            int kby = ks * 32 + gc * 4;       // byte offset of this thread's k-pair
            uint32_t ah[2][4], al[2][4];
            #pragma unroll
            for (int mt = 0; mt < 2; mt++) {
                int r = warpM + mt * 16 + gr;
                const char* p0 = sAh + r * 80 + kby;
                const char* p1 = sAh + (r + 8) * 80 + kby;
                ah[mt][0] = *(const uint32_t*)p0;
                ah[mt][1] = *(const uint32_t*)p1;
                ah[mt][2] = *(const uint32_t*)(p0 + 16);
                ah[mt][3] = *(const uint32_t*)(p1 + 16);
                const char* q0 = sAl + r * 80 + kby;
                const char* q1 = sAl + (r + 8) * 80 + kby;
                al[mt][0] = *(const uint32_t*)q0;
                al[mt][1] = *(const uint32_t*)q1;
                al[mt][2] = *(const uint32_t*)(q0 + 16);
                al[mt][3] = *(const uint32_t*)(q1 + 16);
            }
            #pragma unroll
            for (int nt = 0; nt < 8; nt++) {
                int c = warpN + nt * 8 + gr;
                uint32_t bh[2], bl[2];
                const char* p = sWh + c * 80 + kby;
                bh[0] = *(const uint32_t*)p;
                bh[1] = *(const uint32_t*)(p + 16);
                const char* q = sWl + c * 80 + kby;
                bl[0] = *(const uint32_t*)q;
                bl[1] = *(const uint32_t*)(q + 16);
                #pragma unroll
                for (int mt = 0; mt < 2; mt++) {
                    mma_bf16(acc[mt][nt], ah[mt], bh);
                    mma_bf16(acc[mt][nt], ah[mt], bl);
                    mma_bf16(acc[mt][nt], al[mt], bh);
                }
            }
        }
        __syncthreads();
    }

    // ---- epilogue ----
    #pragma unroll
    for (int mt = 0; mt < 2; mt++) {
        int r0 = m0 + warpM + mt * 16 + gr;
        #pragma unroll
        for (int nt = 0; nt < 8; nt++) {
            int col = n0 + warpN + nt * 8 + 2 * gc;
            float b0 = bias[col], b1 = bias[col + 1];
            #pragma unroll
            for (int half = 0; half < 2; half++) {
                int row = r0 + half * 8;
                float v0 = acc[mt][nt][2 * half + 0] + b0;
                float v1 = acc[mt][nt][2 * half + 1] + b1;
                if (EPI == 1) {
                    v0 = 0.5f * v0 * (1.0f + erff(v0 * 0.70710678118654752f));
                    v1 = 0.5f * v1 * (1.0f + erff(v1 * 0.70710678118654752f));
                    __nv_bfloat16 h0, l0, h1, l1;
                    split2(v0, h0, l0); split2(v1, h1, l1);
                    __nv_bfloat162 ph; ph.x = h0; ph.y = h1;
                    __nv_bfloat162 pl; pl.x = l0; pl.y = l1;
                    size_t base = (size_t)row * N + col;
                    *(__nv_bfloat162*)(Ch + base) = ph;
                    *(__nv_bfloat162*)(Cl + base) = pl;
                } else {
                    if (EPI == 2) {
                        const float2 rv = *(const float2*)(res + (size_t)row * N + col);
                        v0 += rv.x; v1 += rv.y;
                    }
                    float2 o2; o2.x = v0; o2.y = v1;
                    *(float2*)(Cf + (size_t)row * N + col) = o2;
                }
            }
        }
    }
}

// -------------------- flash attention (fp32, causal + ALiBi, dual-bf16 out) -----------
__global__ void __launch_bounds__(128) attn_kernel(
    const float* __restrict__ qkv,
    __nv_bfloat16* __restrict__ oh, __nv_bfloat16* __restrict__ ol)
{
    int b    = blockIdx.z;
    int h    = blockIdx.y;
    int qblk = blockIdx.x;
    int qi   = qblk * 128 + threadIdx.x;

    __shared__ float Ks[32][64];
    __shared__ float Vs[32][64];

    float q[64];
    {
        const float4* qp = (const float4*)(qkv + ((size_t)(b * TSEQ + qi)) * QKVDIM + h * HEADDIM);
        #pragma unroll
        for (int i = 0; i < 16; i++) {
            float4 t4 = qp[i];
            q[4*i+0] = t4.x; q[4*i+1] = t4.y; q[4*i+2] = t4.z; q[4*i+3] = t4.w;
        }
    }

    float o[64];
    #pragma unroll
    for (int d = 0; d < 64; d++) o[d] = 0.f;
    float m = -INFINITY, l = 0.f;
    float slope = exp2f(-0.5f * (float)(h + 1));

    int ntiles = qblk * 4 + 4;

    for (int t = 0; t < ntiles; t++) {
        int kbase = t * 32;
        __syncthreads();
        #pragma unroll
        for (int i = 0; i < 4; i++) {
            int f = threadIdx.x + i * 128;
            int r = f >> 4;
            int c = (f & 15) * 4;
            const float* kp = qkv + ((size_t)(b * TSEQ + kbase + r)) * QKVDIM + DMODEL + h * HEADDIM + c;
            *(float4*)&Ks[r][c] = *(const float4*)kp;
            *(float4*)&Vs[r][c] = *(const float4*)(kp + DMODEL);
        }
        __syncthreads();

        float s[32];
        #pragma unroll
        for (int j = 0; j < 32; j++) {
            float acc2 = 0.f;
            #pragma unroll
            for (int d4 = 0; d4 < 16; d4++) {
                float4 kv = *(const float4*)&Ks[j][d4 * 4];
                acc2 += q[4*d4+0] * kv.x + q[4*d4+1] * kv.y
                      + q[4*d4+2] * kv.z + q[4*d4+3] * kv.w;
            }
            int kpos = kbase + j;
            s[j] = (kpos <= qi) ? (0.125f * acc2 + slope * (float)(kpos - qi)) : -INFINITY;
        }

        float tm = m;
        #pragma unroll
        for (int j = 0; j < 32; j++) tm = fmaxf(tm, s[j]);
        float corr = __expf(m - tm);
        m = tm;
        l *= corr;
        #pragma unroll
        for (int d = 0; d < 64; d++) o[d] *= corr;
        #pragma unroll
        for (int j = 0; j < 32; j++) {
            float p = __expf(s[j] - m);
            l += p;
            #pragma unroll
            for (int d4 = 0; d4 < 16; d4++) {
                float4 vv = *(const float4*)&Vs[j][d4 * 4];
                o[4*d4+0] += p * vv.x; o[4*d4+1] += p * vv.y;
                o[4*d4+2] += p * vv.z; o[4*d4+3] += p * vv.w;
            }
        }
    }

    float inv = 1.0f / l;
    size_t base = ((size_t)(b * TSEQ + qi)) * DMODEL + h * HEADDIM;
    #pragma unroll
    for (int i = 0; i < 32; i++) {
        float v0 = o[2*i+0] * inv;
        float v1 = o[2*i+1] * inv;
        __nv_bfloat16 h0, l0, h1, l1;
        split2(v0, h0, l0); split2(v1, h1, l1);
        __nv_bfloat162 ph; ph.x = h0; ph.y = h1;
        __nv_bfloat162 pl; pl.x = l0; pl.y = l1;
        *(__nv_bfloat162*)(oh + base + 2 * i) = ph;
        *(__nv_bfloat162*)(ol + base + 2 * i) = pl;
    }
}

// -------------------- launch --------------------
extern "C" void kernel_launch(void* const* d_in, const int* in_sizes, int n_in,
                              void* d_out, int out_size)
{
    const float* x        = (const float*)d_in[0];
    const float* in_w     = (const float*)d_in[1];
    const float* in_b     = (const float*)d_in[2];
    const float* out_w    = (const float*)d_in[3];
    const float* out_b    = (const float*)d_in[4];
    const float* f1_w     = (const float*)d_in[5];
    const float* f1_b     = (const float*)d_in[6];
    const float* f2_w     = (const float*)d_in[7];
    const float* f2_b     = (const float*)d_in[8];
    const float* ln1_w    = (const float*)d_in[9];
    const float* ln1_b    = (const float*)d_in[10];
    const float* ln2_w    = (const float*)d_in[11];
    const float* ln2_b    = (const float*)d_in[12];
    const float* final_w  = (const float*)d_in[13];
    const float* final_b  = (const float*)d_in[14];

    float *x_, *qkv_;
    __nv_bfloat16 *xnh, *xnl, *atth, *attl, *hh, *hl;
    __nv_bfloat16 *wih, *wil, *woh, *wol, *w1h, *w1l, *w2h, *w2l;
    cudaGetSymbolAddress((void**)&x_,   g_x);
    cudaGetSymbolAddress((void**)&qkv_, g_qkv);
    cudaGetSymbolAddress((void**)&xnh,  g_xn_h);
    cudaGetSymbolAddress((void**)&xnl,  g_xn_l);
    cudaGetSymbolAddress((void**)&atth, g_att_h);
    cudaGetSymbolAddress((void**)&attl, g_att_l);
    cudaGetSymbolAddress((void**)&hh,   g_h_h);
    cudaGetSymbolAddress((void**)&hl,   g_h_l);
    cudaGetSymbolAddress((void**)&wih,  g_wi_h);
    cudaGetSymbolAddress((void**)&wil,  g_wi_l);
    cudaGetSymbolAddress((void**)&woh,  g_wo_h);
    cudaGetSymbolAddress((void**)&wol,  g_wo_l);
    cudaGetSymbolAddress((void**)&w1h,  g_w1_h);
    cudaGetSymbolAddress((void**)&w1l,  g_w1_l);
    cudaGetSymbolAddress((void**)&w2h,  g_w2_h);
    cudaGetSymbolAddress((void**)&w2l,  g_w2_l);

    cudaFuncSetAttribute(gemm_bf16<0>, cudaFuncAttributeMaxDynamicSharedMemorySize, GEMM_SMEM);
    cudaFuncSetAttribute(gemm_bf16<1>, cudaFuncAttributeMaxDynamicSharedMemorySize, GEMM_SMEM);
    cudaFuncSetAttribute(gemm_bf16<2>, cudaFuncAttributeMaxDynamicSharedMemorySize, GEMM_SMEM);

    // split all weights into hi/lo bf16 planes
    {
        int n4;
        n4 = NLAYER * QKVDIM * DMODEL / 4;
        split_kernel<<<(n4 + 255) / 256, 256>>>((const float4*)in_w,
            (__nv_bfloat162*)wih, (__nv_bfloat162*)wil, n4);
        n4 = NLAYER * DMODEL * DMODEL / 4;
        split_kernel<<<(n4 + 255) / 256, 256>>>((const float4*)out_w,
            (__nv_bfloat162*)woh, (__nv_bfloat162*)wol, n4);
        n4 = NLAYER * FFDIM * DMODEL / 4;
        split_kernel<<<(n4 + 255) / 256, 256>>>((const float4*)f1_w,
            (__nv_bfloat162*)w1h, (__nv_bfloat162*)w1l, n4);
        n4 = NLAYER * DMODEL * FFDIM / 4;
        split_kernel<<<(n4 + 255) / 256, 256>>>((const float4*)f2_w,
            (__nv_bfloat162*)w2h, (__nv_bfloat162*)w2l, n4);
    }

    // residual stream init
    {
        int n4 = ROWS * DMODEL / 4;
        copy_kernel<<<(n4 + 255) / 256, 256>>>((const float4*)x, (float4*)x_, n4);
    }

    dim3 blk256(256);
    for (int i = 0; i < NLAYER; i++) {
        __nv_bfloat16* iwh = wih + (size_t)i * QKVDIM * DMODEL;
        __nv_bfloat16* iwl = wil + (size_t)i * QKVDIM * DMODEL;
        __nv_bfloat16* owh = woh + (size_t)i * DMODEL * DMODEL;
        __nv_bfloat16* owl = wol + (size_t)i * DMODEL * DMODEL;
        __nv_bfloat16* f1h = w1h + (size_t)i * FFDIM * DMODEL;
        __nv_bfloat16* f1l = w1l + (size_t)i * FFDIM * DMODEL;
        __nv_bfloat16* f2h = w2h + (size_t)i * DMODEL * FFDIM;
        __nv_bfloat16* f2l = w2l + (size_t)i * DMODEL * FFDIM;
        const float* ib = in_b  + (size_t)i * QKVDIM;
        const float* ob = out_b + (size_t)i * DMODEL;
        const float* b1 = f1_b  + (size_t)i * FFDIM;
        const float* b2 = f2_b  + (size_t)i * DMODEL;

        // LN1 -> dual xn
        ln_dual_kernel<<<ROWS, blk256>>>(x_, ln1_w + i * DMODEL, ln1_b + i * DMODEL, xnh, xnl);
        // QKV projection (fp32 out)
        gemm_bf16<0><<<dim3(QKVDIM / 128, ROWS / 128), blk256, GEMM_SMEM>>>(
            xnh, xnl, iwh, iwl, ib, nullptr, qkv_, nullptr, nullptr, ROWS, QKVDIM, DMODEL);
        // attention -> dual att
        attn_kernel<<<dim3(TSEQ / 128, NHEAD, BATCH), 128>>>(qkv_, atth, attl);
        // out projection + residual -> x (fp32)
        gemm_bf16<2><<<dim3(DMODEL / 128, ROWS / 128), blk256, GEMM_SMEM>>>(
            atth, attl, owh, owl, ob, x_, x_, nullptr, nullptr, ROWS, DMODEL, DMODEL);
        // LN2 -> dual xn
        ln_dual_kernel<<<ROWS, blk256>>>(x_, ln2_w + i * DMODEL, ln2_b + i * DMODEL, xnh, xnl);
        // FFN1 + GELU -> dual h
        gemm_bf16<1><<<dim3(FFDIM / 128, ROWS / 128), blk256, GEMM_SMEM>>>(
            xnh, xnl, f1h, f1l, b1, nullptr, nullptr, hh, hl, ROWS, FFDIM, DMODEL);
        // FFN2 + residual -> x (fp32)
        gemm_bf16<2><<<dim3(DMODEL / 128, ROWS / 128), blk256, GEMM_SMEM>>>(
            hh, hl, f2h, f2l, b2, x_, x_, nullptr, nullptr, ROWS, DMODEL, FFDIM);
    }
    ln_kernel<<<ROWS, blk256>>>(x_, final_w, final_b, (float*)d_out);
}

// round 10
// speedup vs baseline: 3.0662x; 1.8125x over previous
#include <cuda_runtime.h>
#include <cuda_bf16.h>
#include <math.h>
#include <stdint.h>

// Problem constants
#define TSEQ    2048
#define BATCH   2
#define DMODEL  1024
#define NHEAD   16
#define HEADDIM 64
#define FFDIM   4096
#define NLAYER  4
#define ROWS    (BATCH * TSEQ)          // 4096
#define QKVDIM  (3 * DMODEL)            // 3072
#define QKPITCH (2 * DMODEL)            // 2048 (Q cols 0..1023, K cols 1024..2047)

// -------------------- scratch (allocation-free) --------------------
__device__ float g_x  [ROWS * DMODEL];          // residual stream (fp32)
// dual-bf16 activation planes
__device__ __nv_bfloat16 g_xn_h [ROWS * DMODEL];
__device__ __nv_bfloat16 g_xn_l [ROWS * DMODEL];
__device__ __nv_bfloat16 g_att_h[ROWS * DMODEL];
__device__ __nv_bfloat16 g_att_l[ROWS * DMODEL];
__device__ __nv_bfloat16 g_h_h  [ROWS * FFDIM];
__device__ __nv_bfloat16 g_h_l  [ROWS * FFDIM];
// QK packed planes [row][2048] and V transposed planes [b*H*64 + d][t]
__device__ __nv_bfloat16 g_qk_h [ROWS * QKPITCH];
__device__ __nv_bfloat16 g_qk_l [ROWS * QKPITCH];
__device__ __nv_bfloat16 g_vt_h [BATCH * NHEAD * HEADDIM * TSEQ];
__device__ __nv_bfloat16 g_vt_l [BATCH * NHEAD * HEADDIM * TSEQ];
// dual-bf16 weight planes (split per launch)
__device__ __nv_bfloat16 g_wi_h[NLAYER * QKVDIM * DMODEL];
__device__ __nv_bfloat16 g_wi_l[NLAYER * QKVDIM * DMODEL];
__device__ __nv_bfloat16 g_wo_h[NLAYER * DMODEL * DMODEL];
__device__ __nv_bfloat16 g_wo_l[NLAYER * DMODEL * DMODEL];
__device__ __nv_bfloat16 g_w1_h[NLAYER * FFDIM * DMODEL];
__device__ __nv_bfloat16 g_w1_l[NLAYER * FFDIM * DMODEL];
__device__ __nv_bfloat16 g_w2_h[NLAYER * DMODEL * FFDIM];
__device__ __nv_bfloat16 g_w2_l[NLAYER * DMODEL * FFDIM];

// -------------------- helpers --------------------
__device__ __forceinline__ void cp_async16(uint32_t smem, const void* g) {
    asm volatile("cp.async.cg.shared.global [%0], [%1], 16;\n" :: "r"(smem), "l"(g));
}
__device__ __forceinline__ void cp_commit() {
    asm volatile("cp.async.commit_group;\n" ::: "memory");
}
__device__ __forceinline__ void cp_wait0() {
    asm volatile("cp.async.wait_group 0;\n" ::: "memory");
}
__device__ __forceinline__ uint32_t smem_u32(const void* p) {
    return (uint32_t)__cvta_generic_to_shared(p);
}
__device__ __forceinline__ void split2(float v, __nv_bfloat16& h, __nv_bfloat16& l) {
    h = __float2bfloat16(v);
    l = __float2bfloat16(v - __bfloat162float(h));
}
__device__ __forceinline__ void splitpack(float a, float b, uint32_t& hi, uint32_t& lo) {
    __nv_bfloat16 ha, la, hb, lb;
    split2(a, ha, la); split2(b, hb, lb);
    __nv_bfloat162 ph; ph.x = ha; ph.y = hb;
    __nv_bfloat162 pl; pl.x = la; pl.y = lb;
    hi = *(uint32_t*)&ph; lo = *(uint32_t*)&pl;
}
__device__ __forceinline__ void mma_bf16(float* d, const uint32_t* a, const uint32_t* b) {
    asm volatile(
        "mma.sync.aligned.m16n8k16.row.col.f32.bf16.bf16.f32 "
        "{%0,%1,%2,%3}, {%4,%5,%6,%7}, {%8,%9}, {%0,%1,%2,%3};\n"
        : "+f"(d[0]), "+f"(d[1]), "+f"(d[2]), "+f"(d[3])
        : "r"(a[0]), "r"(a[1]), "r"(a[2]), "r"(a[3]),
          "r"(b[0]), "r"(b[1]));
}

// -------------------- copy --------------------
__global__ void copy_kernel(const float4* __restrict__ in, float4* __restrict__ out, int n4) {
    int i = blockIdx.x * blockDim.x + threadIdx.x;
    if (i < n4) out[i] = in[i];
}

// -------------------- weight split (fp32 -> hi/lo bf16 planes) --------------------
__global__ void split_kernel(const float4* __restrict__ in,
                             __nv_bfloat162* __restrict__ hi,
                             __nv_bfloat162* __restrict__ lo, int n4) {
    int i = blockIdx.x * blockDim.x + threadIdx.x;
    if (i >= n4) return;
    float4 v = in[i];
    uint32_t h0, l0, h1, l1;
    splitpack(v.x, v.y, h0, l0);
    splitpack(v.z, v.w, h1, l1);
    hi[i * 2 + 0] = *(__nv_bfloat162*)&h0; hi[i * 2 + 1] = *(__nv_bfloat162*)&h1;
    lo[i * 2 + 0] = *(__nv_bfloat162*)&l0; lo[i * 2 + 1] = *(__nv_bfloat162*)&l1;
}

// -------------------- layernorm (fp32 out — final) --------------------
__global__ void __launch_bounds__(256) ln_kernel(
    const float* __restrict__ in, const float* __restrict__ w,
    const float* __restrict__ b, float* __restrict__ out)
{
    int row = blockIdx.x;
    int tid = threadIdx.x;
    const float4* ip = (const float4*)(in + (size_t)row * DMODEL);
    float4 v = ip[tid];
    float s  = v.x + v.y + v.z + v.w;
    float sq = v.x * v.x + v.y * v.y + v.z * v.z + v.w * v.w;
    #pragma unroll
    for (int o = 16; o > 0; o >>= 1) {
        s  += __shfl_xor_sync(0xffffffffu, s,  o);
        sq += __shfl_xor_sync(0xffffffffu, sq, o);
    }
    __shared__ float reds[8], redq[8];
    int lane = tid & 31, wid = tid >> 5;
    if (lane == 0) { reds[wid] = s; redq[wid] = sq; }
    __syncthreads();
    float ts = 0.f, tq = 0.f;
    #pragma unroll
    for (int i = 0; i < 8; i++) { ts += reds[i]; tq += redq[i]; }
    float mean = ts * (1.0f / DMODEL);
    float var  = tq * (1.0f / DMODEL) - mean * mean;
    float rstd = rsqrtf(var + 1e-5f);
    float4 wv = ((const float4*)w)[tid];
    float4 bv = ((const float4*)b)[tid];
    float4 r;
    r.x = (v.x - mean) * rstd * wv.x + bv.x;
    r.y = (v.y - mean) * rstd * wv.y + bv.y;
    r.z = (v.z - mean) * rstd * wv.z + bv.z;
    r.w = (v.w - mean) * rstd * wv.w + bv.w;
    ((float4*)(out + (size_t)row * DMODEL))[tid] = r;
}

// -------------------- layernorm (dual-bf16 out) --------------------
__global__ void __launch_bounds__(256) ln_dual_kernel(
    const float* __restrict__ in, const float* __restrict__ w,
    const float* __restrict__ b,
    __nv_bfloat16* __restrict__ oh, __nv_bfloat16* __restrict__ ol)
{
    int row = blockIdx.x;
    int tid = threadIdx.x;
    const float4* ip = (const float4*)(in + (size_t)row * DMODEL);
    float4 v = ip[tid];
    float s  = v.x + v.y + v.z + v.w;
    float sq = v.x * v.x + v.y * v.y + v.z * v.z + v.w * v.w;
    #pragma unroll
    for (int o = 16; o > 0; o >>= 1) {
        s  += __shfl_xor_sync(0xffffffffu, s,  o);
        sq += __shfl_xor_sync(0xffffffffu, sq, o);
    }
    __shared__ float reds[8], redq[8];
    int lane = tid & 31, wid = tid >> 5;
    if (lane == 0) { reds[wid] = s; redq[wid] = sq; }
    __syncthreads();
    float ts = 0.f, tq = 0.f;
    #pragma unroll
    for (int i = 0; i < 8; i++) { ts += reds[i]; tq += redq[i]; }
    float mean = ts * (1.0f / DMODEL);
    float var  = tq * (1.0f / DMODEL) - mean * mean;
    float rstd = rsqrtf(var + 1e-5f);
    float4 wv = ((const float4*)w)[tid];
    float4 bv = ((const float4*)b)[tid];
    float r0 = (v.x - mean) * rstd * wv.x + bv.x;
    float r1 = (v.y - mean) * rstd * wv.y + bv.y;
    float r2 = (v.z - mean) * rstd * wv.z + bv.z;
    float r3 = (v.w - mean) * rstd * wv.w + bv.w;
    uint32_t ph0, pl0, ph1, pl1;
    splitpack(r0, r1, ph0, pl0);
    splitpack(r2, r3, ph1, pl1);
    size_t base = (size_t)row * DMODEL + tid * 4;
    *(uint32_t*)(oh + base)     = ph0;
    *(uint32_t*)(oh + base + 2) = ph1;
    *(uint32_t*)(ol + base)     = pl0;
    *(uint32_t*)(ol + base + 2) = pl1;
}

// -------------------- bf16 split-3 tensor-core GEMM (mma.sync m16n8k16) --------------------
// C[M,N] = A[M,K] @ W[N,K]^T + bias; A,W as hi/lo bf16 planes (K-major).
// Block 128x128, BK=32, 256 threads = 8 warps (4M x 2N), warp tile 32x64.
// EPI: 1 = bias+GELU -> dual-bf16 ; 2 = bias+residual -> fp32 ;
//      3 = bias -> QK dual planes (pitch 2048) + V transposed dual planes
#define GPITCH 40                             // bf16 elements per row in smem
#define A_ELE (128 * GPITCH)
#define W_ELE (128 * GPITCH)
#define STG_ELE (2 * A_ELE + 2 * W_ELE)
#define GEMM_SMEM (2 * STG_ELE * 2)           // 81920 bytes

template <int EPI>
__global__ void __launch_bounds__(256, 2) gemm_bf16(
    const __nv_bfloat16* __restrict__ Ah, const __nv_bfloat16* __restrict__ Al,
    const __nv_bfloat16* __restrict__ Wh, const __nv_bfloat16* __restrict__ Wl,
    const float* __restrict__ bias, const float* __restrict__ res,
    float* __restrict__ Cf, __nv_bfloat16* __restrict__ Ch, __nv_bfloat16* __restrict__ Cl,
    __nv_bfloat16* __restrict__ Vth, __nv_bfloat16* __restrict__ Vtl,
    int M, int N, int K)
{
    extern __shared__ __nv_bfloat16 smem[];
    uint32_t sbase = smem_u32(smem);

    int tid  = threadIdx.x;
    int lane = tid & 31;
    int wid  = tid >> 5;
    int warpM = (wid >> 1) * 32;
    int warpN = (wid & 1) * 64;
    int m0 = blockIdx.y * 128;
    int n0 = blockIdx.x * 128;

    int gr = lane >> 2;
    int gc = lane & 3;

    float acc[2][8][4];
    #pragma unroll
    for (int i = 0; i < 2; i++)
        #pragma unroll
        for (int j = 0; j < 8; j++)
            #pragma unroll
            for (int c = 0; c < 4; c++) acc[i][j][c] = 0.f;

    int KT = K >> 5;

    auto load_chunk = [&](int kt) {
        uint32_t sb = sbase + (uint32_t)(kt & 1) * STG_ELE * 2;
        int k0 = kt << 5;
        #pragma unroll
        for (int i = 0; i < 2; i++) {
            int idx = tid + i * 256;
            int row = idx >> 2;
            int k16 = idx & 3;
            uint32_t so = (uint32_t)(row * 80 + k16 * 16);
            size_t ga = (size_t)(m0 + row) * K + k0 + k16 * 8;
            size_t gw = (size_t)(n0 + row) * K + k0 + k16 * 8;
            cp_async16(sb + so, Ah + ga);
            cp_async16(sb + A_ELE * 2 + so, Al + ga);
            cp_async16(sb + 2 * A_ELE * 2 + so, Wh + gw);
            cp_async16(sb + (2 * A_ELE + W_ELE) * 2 + so, Wl + gw);
        }
        cp_commit();
    };

    load_chunk(0);

    for (int kt = 0; kt < KT; kt++) {
        cp_wait0();
        __syncthreads();
        if (kt + 1 < KT) load_chunk(kt + 1);

        const char* stg = (const char*)smem + (size_t)(kt & 1) * STG_ELE * 2;
        const char* sAh = stg;
        const char* sAl = stg + A_ELE * 2;
        const char* sWh = stg + 2 * A_ELE * 2;
        const char* sWl = stg + (2 * A_ELE + W_ELE) * 2;

        #pragma unroll
        for (int ks = 0; ks < 2; ks++) {
            int kby = ks * 32 + gc * 4;
            uint32_t ah[2][4], al[2][4];
            #pragma unroll
            for (int mt = 0; mt < 2; mt++) {
                int r = warpM + mt * 16 + gr;
                const char* p0 = sAh + r * 80 + kby;
                const char* p1 = sAh + (r + 8) * 80 + kby;
                ah[mt][0] = *(const uint32_t*)p0;
                ah[mt][1] = *(const uint32_t*)p1;
                ah[mt][2] = *(const uint32_t*)(p0 + 16);
                ah[mt][3] = *(const uint32_t*)(p1 + 16);
                const char* q0 = sAl + r * 80 + kby;
                const char* q1 = sAl + (r + 8) * 80 + kby;
                al[mt][0] = *(const uint32_t*)q0;
                al[mt][1] = *(const uint32_t*)q1;
                al[mt][2] = *(const uint32_t*)(q0 + 16);
                al[mt][3] = *(const uint32_t*)(q1 + 16);
            }
            #pragma unroll
            for (int nt = 0; nt < 8; nt++) {
                int c = warpN + nt * 8 + gr;
                uint32_t bh[2], bl[2];
                const char* p = sWh + c * 80 + kby;
                bh[0] = *(const uint32_t*)p;
                bh[1] = *(const uint32_t*)(p + 16);
                const char* q = sWl + c * 80 + kby;
                bl[0] = *(const uint32_t*)q;
                bl[1] = *(const uint32_t*)(q + 16);
                #pragma unroll
                for (int mt = 0; mt < 2; mt++) {
                    mma_bf16(acc[mt][nt], ah[mt], bh);
                    mma_bf16(acc[mt][nt], ah[mt], bl);
                    mma_bf16(acc[mt][nt], al[mt], bh);
                }
            }
        }
        __syncthreads();
    }

    // ---- epilogue ----
    #pragma unroll
    for (int mt = 0; mt < 2; mt++) {
        int r0 = m0 + warpM + mt * 16 + gr;
        #pragma unroll
        for (int nt = 0; nt < 8; nt++) {
            int col = n0 + warpN + nt * 8 + 2 * gc;
            float b0 = bias[col], b1 = bias[col + 1];
            #pragma unroll
            for (int half = 0; half < 2; half++) {
                int row = r0 + half * 8;
                float v0 = acc[mt][nt][2 * half + 0] + b0;
                float v1 = acc[mt][nt][2 * half + 1] + b1;
                if (EPI == 1) {
                    v0 = 0.5f * v0 * (1.0f + erff(v0 * 0.70710678118654752f));
                    v1 = 0.5f * v1 * (1.0f + erff(v1 * 0.70710678118654752f));
                    uint32_t ph, pl;
                    splitpack(v0, v1, ph, pl);
                    size_t base = (size_t)row * N + col;
                    *(uint32_t*)(Ch + base) = ph;
                    *(uint32_t*)(Cl + base) = pl;
                } else if (EPI == 2) {
                    const float2 rv = *(const float2*)(res + (size_t)row * N + col);
                    v0 += rv.x; v1 += rv.y;
                    float2 o2; o2.x = v0; o2.y = v1;
                    *(float2*)(Cf + (size_t)row * N + col) = o2;
                } else {   // EPI == 3: QKV epilogue
                    if (col >= 2 * DMODEL) {
                        int c  = col - 2 * DMODEL;
                        int hh = c >> 6, d = c & 63;
                        int bb = row >> 11, t = row & (TSEQ - 1);
                        size_t vi = ((size_t)((bb * NHEAD + hh) * HEADDIM + d)) * TSEQ + t;
                        __nv_bfloat16 h0, l0v, h1, l1v;
                        split2(v0, h0, l0v); split2(v1, h1, l1v);
                        Vth[vi] = h0;        Vtl[vi] = l0v;
                        Vth[vi + TSEQ] = h1; Vtl[vi + TSEQ] = l1v;
                    } else {
                        uint32_t ph, pl;
                        splitpack(v0, v1, ph, pl);
                        size_t base = (size_t)row * QKPITCH + col;
                        *(uint32_t*)(Ch + base) = ph;
                        *(uint32_t*)(Cl + base) = pl;
                    }
                }
            }
        }
    }
}

// -------------------- mma flash attention (bf16 split-3, causal + ALiBi) --------------------
// Grid (T/64, H, B), 128 threads = 4 warps, each warp 16 query rows.
// K tile 64x64 from qk planes (K-major, like weights); V from transposed planes.
#define KV_PITCH_B 144                         // smem row pitch bytes (72 bf16)
#define KV_TILE_B (64 * KV_PITCH_B)            // 9216 per plane
#define ATT_STAGE (4 * KV_TILE_B)              // Kh,Kl,Vh,Vl
#define ATT_SMEM  (2 * ATT_STAGE)              // 73728

__global__ void __launch_bounds__(128) attn_mma_kernel(
    const __nv_bfloat16* __restrict__ qkh, const __nv_bfloat16* __restrict__ qkl,
    const __nv_bfloat16* __restrict__ vth, const __nv_bfloat16* __restrict__ vtl,
    __nv_bfloat16* __restrict__ oh, __nv_bfloat16* __restrict__ ol)
{
    extern __shared__ char asmem[];
    uint32_t sbase = smem_u32(asmem);

    int b = blockIdx.z, h = blockIdx.y;
    int qt = gridDim.x - 1 - blockIdx.x;       // big tiles first
    int tid = threadIdx.x, lane = tid & 31, w = tid >> 5;
    int gr = lane >> 2, gc = lane & 3;

    int hcol = h * HEADDIM;
    int qrow0 = b * TSEQ + qt * 64;            // global gmem row of first query

    // Q fragments (per kc: a0..a3), hi and lo
    uint32_t qh[4][4], ql[4][4];
    {
        const __nv_bfloat16* qp  = qkh + (size_t)(qrow0 + w * 16) * QKPITCH + hcol;
        const __nv_bfloat16* qpl = qkl + (size_t)(qrow0 + w * 16) * QKPITCH + hcol;
        #pragma unroll
        for (int kc = 0; kc < 4; kc++) {
            int c = kc * 16 + 2 * gc;
            qh[kc][0] = *(const uint32_t*)(qp  + (size_t)gr * QKPITCH + c);
            qh[kc][1] = *(const uint32_t*)(qp  + (size_t)(gr + 8) * QKPITCH + c);
            qh[kc][2] = *(const uint32_t*)(qp  + (size_t)gr * QKPITCH + c + 8);
            qh[kc][3] = *(const uint32_t*)(qp  + (size_t)(gr + 8) * QKPITCH + c + 8);
            ql[kc][0] = *(const uint32_t*)(qpl + (size_t)gr * QKPITCH + c);
            ql[kc][1] = *(const uint32_t*)(qpl + (size_t)(gr + 8) * QKPITCH + c);
            ql[kc][2] = *(const uint32_t*)(qpl + (size_t)gr * QKPITCH + c + 8);
            ql[kc][3] = *(const uint32_t*)(qpl + (size_t)(gr + 8) * QKPITCH + c + 8);
        }
    }

    auto load_kv = [&](int kt, int s) {
        uint32_t sb = sbase + (uint32_t)s * ATT_STAGE;
        const __nv_bfloat16* Kh = qkh + (size_t)(b * TSEQ + kt * 64) * QKPITCH + DMODEL + hcol;
        const __nv_bfloat16* Kl = qkl + (size_t)(b * TSEQ + kt * 64) * QKPITCH + DMODEL + hcol;
        size_t vbase = (size_t)((b * NHEAD + h) * HEADDIM) * TSEQ + kt * 64;
        #pragma unroll
        for (int i = 0; i < 4; i++) {
            int idx = tid + i * 128;          // 0..511
            int r   = idx >> 3;               // 0..63
            int c16 = idx & 7;                // 0..7
            uint32_t so = (uint32_t)(r * KV_PITCH_B + c16 * 16);
            cp_async16(sb + so,                  Kh  + (size_t)r * QKPITCH + c16 * 8);
            cp_async16(sb + KV_TILE_B + so,      Kl  + (size_t)r * QKPITCH + c16 * 8);
            cp_async16(sb + 2 * KV_TILE_B + so,  vth + vbase + (size_t)r * TSEQ + c16 * 8);
            cp_async16(sb + 3 * KV_TILE_B + so,  vtl + vbase + (size_t)r * TSEQ + c16 * 8);
        }
        cp_commit();
    };

    float m0 = -INFINITY, m1 = -INFINITY, l0 = 0.f, l1 = 0.f;
    float acc_o[8][4];
    #pragma unroll
    for (int nt = 0; nt < 8; nt++)
        #pragma unroll
        for (int j = 0; j < 4; j++) acc_o[nt][j] = 0.f;

    float slope = exp2f(-0.5f * (float)(h + 1));
    int qpos0 = qt * 64 + w * 16 + gr;        // sequence position of row0

    load_kv(0, 0);

    for (int kt = 0; kt <= qt; kt++) {
        int s = kt & 1;
        cp_wait0();
        __syncthreads();
        if (kt < qt) load_kv(kt + 1, s ^ 1);

        const char* Ksh = asmem + (size_t)s * ATT_STAGE;
        const char* Ksl = Ksh + KV_TILE_B;
        const char* Vsh = Ksh + 2 * KV_TILE_B;
        const char* Vsl = Ksh + 3 * KV_TILE_B;

        // ---- S = Q K^T ----
        float sacc[8][4];
        #pragma unroll
        for (int nt = 0; nt < 8; nt++)
            #pragma unroll
            for (int j = 0; j < 4; j++) sacc[nt][j] = 0.f;

        #pragma unroll
        for (int kc = 0; kc < 4; kc++) {
            int kby = kc * 32 + gc * 4;
            #pragma unroll
            for (int nt = 0; nt < 8; nt++) {
                int c = nt * 8 + gr;
                uint32_t bh[2], bl[2];
                const char* p = Ksh + c * KV_PITCH_B + kby;
                bh[0] = *(const uint32_t*)p; bh[1] = *(const uint32_t*)(p + 16);
                const char* q = Ksl + c * KV_PITCH_B + kby;
                bl[0] = *(const uint32_t*)q; bl[1] = *(const uint32_t*)(q + 16);
                mma_bf16(sacc[nt], qh[kc], bh);
                mma_bf16(sacc[nt], qh[kc], bl);
                mma_bf16(sacc[nt], ql[kc], bh);
            }
        }

        // ---- mask + ALiBi + online softmax ----
        int kbase = kt * 64;
        float tmax0 = -INFINITY, tmax1 = -INFINITY;
        #pragma unroll
        for (int nt = 0; nt < 8; nt++) {
            #pragma unroll
            for (int j = 0; j < 4; j++) {
                int kp = kbase + nt * 8 + 2 * gc + (j & 1);
                int qp = qpos0 + ((j >> 1) << 3);
                float sv = (kp <= qp)
                    ? sacc[nt][j] * 0.125f + slope * (float)(kp - qp)
                    : -INFINITY;
                sacc[nt][j] = sv;
                if (j < 2) tmax0 = fmaxf(tmax0, sv);
                else       tmax1 = fmaxf(tmax1, sv);
            }
        }
        tmax0 = fmaxf(tmax0, __shfl_xor_sync(0xffffffffu, tmax0, 1));
        tmax0 = fmaxf(tmax0, __shfl_xor_sync(0xffffffffu, tmax0, 2));
        tmax1 = fmaxf(tmax1, __shfl_xor_sync(0xffffffffu, tmax1, 1));
        tmax1 = fmaxf(tmax1, __shfl_xor_sync(0xffffffffu, tmax1, 2));

        float nm0 = fmaxf(m0, tmax0);
        float nm1 = fmaxf(m1, tmax1);
        float corr0 = __expf(m0 - nm0);
        float corr1 = __expf(m1 - nm1);
        m0 = nm0; m1 = nm1;
        l0 *= corr0; l1 *= corr1;
        #pragma unroll
        for (int nt = 0; nt < 8; nt++) {
            acc_o[nt][0] *= corr0; acc_o[nt][1] *= corr0;
            acc_o[nt][2] *= corr1; acc_o[nt][3] *= corr1;
        }

        float ts0 = 0.f, ts1 = 0.f;
        #pragma unroll
        for (int nt = 0; nt < 8; nt++) {
            #pragma unroll
            for (int j = 0; j < 4; j++) {
                float p = __expf(sacc[nt][j] - ((j < 2) ? m0 : m1));
                sacc[nt][j] = p;
                if (j < 2) ts0 += p; else ts1 += p;
            }
        }
        ts0 += __shfl_xor_sync(0xffffffffu, ts0, 1);
        ts0 += __shfl_xor_sync(0xffffffffu, ts0, 2);
        ts1 += __shfl_xor_sync(0xffffffffu, ts1, 1);
        ts1 += __shfl_xor_sync(0xffffffffu, ts1, 2);
        l0 += ts0; l1 += ts1;

        // ---- O += P V  (P packed from sacc; A-frag = acc layout) ----
        #pragma unroll
        for (int kc = 0; kc < 4; kc++) {
            uint32_t ph[4], pl[4];
            splitpack(sacc[2 * kc][0],     sacc[2 * kc][1],     ph[0], pl[0]);
            splitpack(sacc[2 * kc][2],     sacc[2 * kc][3],     ph[1], pl[1]);
            splitpack(sacc[2 * kc + 1][0], sacc[2 * kc + 1][1], ph[2], pl[2]);
            splitpack(sacc[2 * kc + 1][2], sacc[2 * kc + 1][3], ph[3], pl[3]);
            int kby = kc * 32 + gc * 4;
            #pragma unroll
            for (int nt = 0; nt < 8; nt++) {
                int c = nt * 8 + gr;
                uint32_t bh[2], bl[2];
                const char* p = Vsh + c * KV_PITCH_B + kby;
                bh[0] = *(const uint32_t*)p; bh[1] = *(const uint32_t*)(p + 16);
                const char* q = Vsl + c * KV_PITCH_B + kby;
                bl[0] = *(const uint32_t*)q; bl[1] = *(const uint32_t*)(q + 16);
                mma_bf16(acc_o[nt], ph, bh);
                mma_bf16(acc_o[nt], ph, bl);
                mma_bf16(acc_o[nt], pl, bh);
            }
        }
    }

    // ---- epilogue: divide by l, write dual-bf16 ----
    float inv0 = 1.0f / l0, inv1 = 1.0f / l1;
    int r0 = qrow0 + w * 16 + gr;
    #pragma unroll
    for (int nt = 0; nt < 8; nt++) {
        int col = hcol + nt * 8 + 2 * gc;
        uint32_t ph0, pl0, ph1, pl1;
        splitpack(acc_o[nt][0] * inv0, acc_o[nt][1] * inv0, ph0, pl0);
        splitpack(acc_o[nt][2] * inv1, acc_o[nt][3] * inv1, ph1, pl1);
        size_t b0 = (size_t)r0 * DMODEL + col;
        size_t b1 = (size_t)(r0 + 8) * DMODEL + col;
        *(uint32_t*)(oh + b0) = ph0; *(uint32_t*)(ol + b0) = pl0;
        *(uint32_t*)(oh + b1) = ph1; *(uint32_t*)(ol + b1) = pl1;
    }
}

// -------------------- launch --------------------
extern "C" void kernel_launch(void* const* d_in, const int* in_sizes, int n_in,
                              void* d_out, int out_size)
{
    const float* x        = (const float*)d_in[0];
    const float* in_w     = (const float*)d_in[1];
    const float* in_b     = (const float*)d_in[2];
    const float* out_w    = (const float*)d_in[3];
    const float* out_b    = (const float*)d_in[4];
    const float* f1_w     = (const float*)d_in[5];
    const float* f1_b     = (const float*)d_in[6];
    const float* f2_w     = (const float*)d_in[7];
    const float* f2_b     = (const float*)d_in[8];
    const float* ln1_w    = (const float*)d_in[9];
    const float* ln1_b    = (const float*)d_in[10];
    const float* ln2_w    = (const float*)d_in[11];
    const float* ln2_b    = (const float*)d_in[12];
    const float* final_w  = (const float*)d_in[13];
    const float* final_b  = (const float*)d_in[14];

    float *x_;
    __nv_bfloat16 *xnh, *xnl, *atth, *attl, *hh, *hl;
    __nv_bfloat16 *qkh, *qkl, *vth, *vtl;
    __nv_bfloat16 *wih, *wil, *woh, *wol, *w1h, *w1l, *w2h, *w2l;
    cudaGetSymbolAddress((void**)&x_,   g_x);
    cudaGetSymbolAddress((void**)&xnh,  g_xn_h);
    cudaGetSymbolAddress((void**)&xnl,  g_xn_l);
    cudaGetSymbolAddress((void**)&atth, g_att_h);
    cudaGetSymbolAddress((void**)&attl, g_att_l);
    cudaGetSymbolAddress((void**)&hh,   g_h_h);
    cudaGetSymbolAddress((void**)&hl,   g_h_l);
    cudaGetSymbolAddress((void**)&qkh,  g_qk_h);
    cudaGetSymbolAddress((void**)&qkl,  g_qk_l);
    cudaGetSymbolAddress((void**)&vth,  g_vt_h);
    cudaGetSymbolAddress((void**)&vtl,  g_vt_l);
    cudaGetSymbolAddress((void**)&wih,  g_wi_h);
    cudaGetSymbolAddress((void**)&wil,  g_wi_l);
    cudaGetSymbolAddress((void**)&woh,  g_wo_h);
    cudaGetSymbolAddress((void**)&wol,  g_wo_l);
    cudaGetSymbolAddress((void**)&w1h,  g_w1_h);
    cudaGetSymbolAddress((void**)&w1l,  g_w1_l);
    cudaGetSymbolAddress((void**)&w2h,  g_w2_h);
    cudaGetSymbolAddress((void**)&w2l,  g_w2_l);

    cudaFuncSetAttribute(gemm_bf16<1>, cudaFuncAttributeMaxDynamicSharedMemorySize, GEMM_SMEM);
    cudaFuncSetAttribute(gemm_bf16<2>, cudaFuncAttributeMaxDynamicSharedMemorySize, GEMM_SMEM);
    cudaFuncSetAttribute(gemm_bf16<3>, cudaFuncAttributeMaxDynamicSharedMemorySize, GEMM_SMEM);
    cudaFuncSetAttribute(attn_mma_kernel, cudaFuncAttributeMaxDynamicSharedMemorySize, ATT_SMEM);

    // split all weights into hi/lo bf16 planes
    {
        int n4;
        n4 = NLAYER * QKVDIM * DMODEL / 4;
        split_kernel<<<(n4 + 255) / 256, 256>>>((const float4*)in_w,
            (__nv_bfloat162*)wih, (__nv_bfloat162*)wil, n4);
        n4 = NLAYER * DMODEL * DMODEL / 4;
        split_kernel<<<(n4 + 255) / 256, 256>>>((const float4*)out_w,
            (__nv_bfloat162*)woh, (__nv_bfloat162*)wol, n4);
        n4 = NLAYER * FFDIM * DMODEL / 4;
        split_kernel<<<(n4 + 255) / 256, 256>>>((const float4*)f1_w,
            (__nv_bfloat162*)w1h, (__nv_bfloat162*)w1l, n4);
        n4 = NLAYER * DMODEL * FFDIM / 4;
        split_kernel<<<(n4 + 255) / 256, 256>>>((const float4*)f2_w,
            (__nv_bfloat162*)w2h, (__nv_bfloat162*)w2l, n4);
    }

    // residual stream init
    {
        int n4 = ROWS * DMODEL / 4;
        copy_kernel<<<(n4 + 255) / 256, 256>>>((const float4*)x, (float4*)x_, n4);
    }

    dim3 blk256(256);
    for (int i = 0; i < NLAYER; i++) {
        __nv_bfloat16* iwh = wih + (size_t)i * QKVDIM * DMODEL;
        __nv_bfloat16* iwl = wil + (size_t)i * QKVDIM * DMODEL;
        __nv_bfloat16* owh = woh + (size_t)i * DMODEL * DMODEL;
        __nv_bfloat16* owl = wol + (size_t)i * DMODEL * DMODEL;
        __nv_bfloat16* f1h = w1h + (size_t)i * FFDIM * DMODEL;
        __nv_bfloat16* f1l = w1l + (size_t)i * FFDIM * DMODEL;
        __nv_bfloat16* f2h = w2h + (size_t)i * DMODEL * FFDIM;
        __nv_bfloat16* f2l = w2l + (size_t)i * DMODEL * FFDIM;
        const float* ib = in_b  + (size_t)i * QKVDIM;
        const float* ob = out_b + (size_t)i * DMODEL;
        const float* b1 = f1_b  + (size_t)i * FFDIM;
        const float* b2 = f2_b  + (size_t)i * DMODEL;

        // LN1 -> dual xn
        ln_dual_kernel<<<ROWS, blk256>>>(x_, ln1_w + i * DMODEL, ln1_b + i * DMODEL, xnh, xnl);
        // QKV projection -> QK dual planes + V transposed dual planes
        gemm_bf16<3><<<dim3(QKVDIM / 128, ROWS / 128), blk256, GEMM_SMEM>>>(
            xnh, xnl, iwh, iwl, ib, nullptr, nullptr, qkh, qkl, vth, vtl,
            ROWS, QKVDIM, DMODEL);
        // attention (mma flash) -> dual att
        attn_mma_kernel<<<dim3(TSEQ / 64, NHEAD, BATCH), 128, ATT_SMEM>>>(
            qkh, qkl, vth, vtl, atth, attl);
        // out projection + residual -> x (fp32)
        gemm_bf16<2><<<dim3(DMODEL / 128, ROWS / 128), blk256, GEMM_SMEM>>>(
            atth, attl, owh, owl, ob, x_, x_, nullptr, nullptr, nullptr, nullptr,
            ROWS, DMODEL, DMODEL);
        // LN2 -> dual xn
        ln_dual_kernel<<<ROWS, blk256>>>(x_, ln2_w + i * DMODEL, ln2_b + i * DMODEL, xnh, xnl);
        // FFN1 + GELU -> dual h
        gemm_bf16<1><<<dim3(FFDIM / 128, ROWS / 128), blk256, GEMM_SMEM>>>(
            xnh, xnl, f1h, f1l, b1, nullptr, nullptr, hh, hl, nullptr, nullptr,
            ROWS, FFDIM, DMODEL);
        // FFN2 + residual -> x (fp32)
        gemm_bf16<2><<<dim3(DMODEL / 128, ROWS / 128), blk256, GEMM_SMEM>>>(
            hh, hl, f2h, f2l, b2, x_, x_, nullptr, nullptr, nullptr, nullptr,
            ROWS, DMODEL, FFDIM);
    }
    ln_kernel<<<ROWS, blk256>>>(x_, final_w, final_b, (float*)d_out);
}